// round 4
// baseline (speedup 1.0000x reference)
#include <cuda_runtime.h>
#include <cstdint>

#define N_DENSE    64
#define N_SAMPLES  121
#define N_CHANNELS 384
#define BATCH      2048
#define ROW_IN     (N_DENSE * (1 + N_SAMPLES))   // 7808 floats per input row
#define ROW_OUT    (N_CHANNELS * N_SAMPLES)      // 46464 floats per output batch
#define N_VEC      (ROW_OUT / 4)                 // 11616 float4 per batch row
#define DATA_F     (N_DENSE * N_SAMPLES)         // 7744 floats of sample data
#define NTHREADS   512
#define NWARPS     (NTHREADS / 32)

// One CTA per batch element. Channel-pure warps:
//   warp w owns channels w, w+16, ... (24 channels). For each channel, lanes
//   cover its ~30 fully-contained output vec4s plus its straddle vec4
//   (consecutive v -> coalesced stores). head[c] is a warp-uniform broadcast
//   LDS and the chain walk is a uniform branch -> zero divergence, no fat
//   per-warp slow path.
__global__ __launch_bounds__(NTHREADS, 3)
void sparse_input_gather_v4(const float* __restrict__ in,
                            float* __restrict__ out)
{
    __shared__ float sdata[DATA_F + 16];  // staged [64][121] + slack for straddle-lane reads
    __shared__ int   head[N_CHANNELS];
    __shared__ int   nxt[N_DENSE];

    const int b = blockIdx.x;
    const int t = threadIdx.x;
    const int w = t >> 5;
    const int l = t & 31;

    const float* __restrict__ row  = in + (size_t)b * ROW_IN;
    const float* __restrict__ data = row + N_DENSE;

    // ---- phase 1: stage data + build inverted index ----
    int my_c = -1;
    if (t < N_DENSE) {
        int c = (int)__ldg(&row[t]);
        my_c = max(0, min(N_CHANNELS - 1, c));
    }
    if (t < N_CHANNELS) head[t] = -1;

    {
        const float4* __restrict__ src = reinterpret_cast<const float4*>(data);
        float4* __restrict__ dst = reinterpret_cast<float4*>(sdata);
        #pragma unroll
        for (int i = t; i < DATA_F / 4; i += NTHREADS)
            dst[i] = src[i];
    }
    __syncthreads();
    if (t < N_DENSE)
        nxt[t] = atomicExch(&head[my_c], t);
    __syncthreads();

    // ---- phase 2: gather, channel-pure warps ----
    float4* __restrict__ ovec = reinterpret_cast<float4*>(out + (size_t)b * ROW_OUT);

    int c    = w;
    int base = N_SAMPLES * w;                 // flat float offset of channel c

    #pragma unroll 4
    for (int k = 0; k < N_CHANNELS / NWARPS; k++) {
        const int vfirst = (base + 3) >> 2;           // first vec4 owned by channel c
        const int vend   = (base + N_SAMPLES + 3) >> 2; // exclusive (incl. straddle)
        const int v      = vfirst + l;
        const bool active = (v < vend);               // 30 or 31 active lanes
        const int s0     = (v << 2) - base;           // in-channel sample of elem 0
        const int nA     = N_SAMPLES - s0;            // elems of this vec4 in channel c

        float4 acc = make_float4(0.f, 0.f, 0.f, 0.f);

        // chain of channel c (warp-uniform walk)
        int d = head[c];
        while (d >= 0) {
            const float* g = sdata + d * N_SAMPLES + s0;
            if (nA > 0) acc.x += g[0];
            if (nA > 1) acc.y += g[1];
            if (nA > 2) acc.z += g[2];
            if (nA > 3) acc.w += g[3];
            d = nxt[d];
        }

        // straddle part from channel c+1 (exists iff 121*(c+1) not 4-aligned)
        if ((base + N_SAMPLES) & 3) {
            int d2 = head[c + 1];                     // uniform
            while (d2 >= 0) {
                const float* g2 = sdata + d2 * N_SAMPLES - nA;
                if (nA < 2 && nA > -2) acc.y += g2[1];
                if (nA < 3 && nA > -1) acc.z += g2[2];
                if (nA < 4 && nA >  0) acc.w += g2[3];
                d2 = nxt[d2];
            }
        }

        if (active) __stcs(&ovec[v], acc);

        c    += NWARPS;
        base += N_SAMPLES * NWARPS;
    }
}

extern "C" void kernel_launch(void* const* d_in, const int* in_sizes, int n_in,
                              void* d_out, int out_size)
{
    const float* in  = (const float*)d_in[0];
    float*       out = (float*)d_out;
    sparse_input_gather_v4<<<BATCH, NTHREADS>>>(in, out);
}